// round 4
// baseline (speedup 1.0000x reference)
#include <cuda_runtime.h>
#include <cstdint>

// ---------------------------------------------------------------------------
// RNG mapping (verified R1, rel_err 5.4e-8): threefry_partitionable,
// bits[i] = x0 ^ x1 of threefry2x32(key=(0,42), ctr=(0,i)), keep = (bits>>9) < 838861
// ---------------------------------------------------------------------------
static constexpr int Bc = 4, Hc = 16, Sc = 2048, Dc = 64;
static constexpr int QT = 128, KT = 128;
static constexpr int NT = 256;

// smem layout (floats): Q[128][64] | Kt[64][128] swizzled | V[128][64] | P[128][128]
static constexpr int SQ_OFF = 0;
static constexpr int SK_OFF = SQ_OFF + QT * Dc;     // 8192
static constexpr int SV_OFF = SK_OFF + Dc * KT;     // 16384
static constexpr int SP_OFF = SV_OFF + KT * Dc;     // 24576
static constexpr int SMEM_FLOATS = SP_OFF + QT * KT; // 40960 -> 160KB

typedef unsigned long long u64;

__device__ __forceinline__ void threefry2x32(uint32_t c0, uint32_t c1,
                                             uint32_t& o0, uint32_t& o1)
{
    const uint32_t K0 = 0u, K1 = 42u;
    const uint32_t K2 = 0x1BD11BDAu ^ K0 ^ K1;
    uint32_t x0 = c0 + K0;
    uint32_t x1 = c1 + K1;
#define TF_R(r) { x0 += x1; x1 = __funnelshift_l(x1, x1, (r)); x1 ^= x0; }
    TF_R(13) TF_R(15) TF_R(26) TF_R(6)
    x0 += K1; x1 += K2 + 1u;
    TF_R(17) TF_R(29) TF_R(16) TF_R(24)
    x0 += K2; x1 += K0 + 2u;
    TF_R(13) TF_R(15) TF_R(26) TF_R(6)
    x0 += K0; x1 += K1 + 3u;
    TF_R(17) TF_R(29) TF_R(16) TF_R(24)
    x0 += K1; x1 += K2 + 4u;
    TF_R(13) TF_R(15) TF_R(26) TF_R(6)
    x0 += K2; x1 += K0 + 5u;
#undef TF_R
    o0 = x0; o1 = x1;
}

__device__ __forceinline__ bool keep_mask(uint32_t bh, uint32_t gq, uint32_t gk)
{
    uint32_t i = (bh << 22) | (gq << 11) | gk;
    uint32_t b0, b1;
    threefry2x32(0u, i, b0, b1);
    return ((b0 ^ b1) >> 9) < 838861u;
}

// ---- f32x2 packed math (sm_103a double-rate fp32) -------------------------
__device__ __forceinline__ u64 dup2(float x)
{ u64 r; asm("mov.b64 %0, {%1, %1};" : "=l"(r) : "f"(x)); return r; }
__device__ __forceinline__ void fma2(u64& d, u64 a, u64 b)
{ asm("fma.rn.f32x2 %0, %1, %2, %0;" : "+l"(d) : "l"(a), "l"(b)); }
__device__ __forceinline__ u64 mul2(u64 a, u64 b)
{ u64 r; asm("mul.rn.f32x2 %0, %1, %2;" : "=l"(r) : "l"(a), "l"(b)); return r; }
__device__ __forceinline__ void unpack2(u64 v, float& lo, float& hi)
{ asm("mov.b64 {%0, %1}, %2;" : "=f"(lo), "=f"(hi) : "l"(v)); }

__device__ __forceinline__ float f4c(const float4 v, int t)
{ return t == 0 ? v.x : t == 1 ? v.y : t == 2 ? v.z : v.w; }

__global__ void __launch_bounds__(NT, 1)
attn_kernel(const float* __restrict__ gq, const float* __restrict__ gk,
            const float* __restrict__ gv, float* __restrict__ gout)
{
    extern __shared__ float sm[];
    float* sQ = sm + SQ_OFF;
    float* sK = sm + SK_OFF;   // transposed [d][k], XOR-swizzled granules
    float* sV = sm + SV_OFF;   // natural [k][d]
    float* sP = sm + SP_OFF;   // natural [q][k], warp-private 16-row slabs

    const int tid = threadIdx.x;
    const int ty = tid >> 4;          // 0..15 -> 8 q-rows each
    const int tx = tid & 15;          // 0..15 -> k-cols {4tx..} U {64+4tx..}
    const int rowb = ty * 8;
    // 16-lane member mask for intra-half reductions (halves can diverge!)
    const uint32_t hm = (tid & 16) ? 0xffff0000u : 0x0000ffffu;
    const uint32_t bh = blockIdx.y;
    const int q0 = blockIdx.x * QT;

    const float* qb  = gq + ((size_t)bh * Sc + q0) * Dc;
    const float* kb0 = gk + (size_t)bh * Sc * Dc;
    const float* vb0 = gv + (size_t)bh * Sc * Dc;

    // ---- load Q tile (pre-scaled by sqrt(D)=8) ----
#pragma unroll
    for (int it = 0; it < 8; ++it) {
        int idx = tid + it * NT;
        int row = idx >> 4, c4 = (idx & 15) << 2;
        float4 v = *(const float4*)(qb + row * Dc + c4);
        v.x *= 8.f; v.y *= 8.f; v.z *= 8.f; v.w *= 8.f;
        *(float4*)&sQ[row * Dc + c4] = v;
    }

    u64 o2[8][2];
    float m[8], l[8];
#pragma unroll
    for (int r = 0; r < 8; ++r) {
        o2[r][0] = 0ull; o2[r][1] = 0ull;
        m[r] = -1e30f; l[r] = 0.f;
    }

    for (int kt = 0; kt < Sc / KT; ++kt) {
        __syncthreads();   // all warps done reading sK/sV of prior iter

        const float* kb = kb0 + (size_t)kt * KT * Dc;
        const float* vb = vb0 + (size_t)kt * KT * Dc;
#pragma unroll
        for (int it = 0; it < 8; ++it) {
            int idx = tid + it * NT;
            int krow = idx >> 4, c4 = (idx & 15) << 2;
            float4 kv = *(const float4*)(kb + krow * Dc + c4);
            int kg = krow >> 2, ko = krow & 3;
#pragma unroll
            for (int i = 0; i < 4; ++i) {
                int d = c4 + i;
                int pg = kg ^ ((d >> 2) & 15);     // swizzle (low 4 bits only)
                sK[d * KT + (pg << 2) + ko] = f4c(kv, i);
            }
            float4 vv = *(const float4*)(vb + krow * Dc + c4);
            *(float4*)&sV[krow * Dc + c4] = vv;
        }
        __syncthreads();

        // ---- S = (8Q) K^T, 8x8 per thread, f32x2 packed over k-pairs ----
        u64 c2[8][4];
#pragma unroll
        for (int r = 0; r < 8; ++r)
#pragma unroll
            for (int j = 0; j < 4; ++j) c2[r][j] = 0ull;

#pragma unroll 4
        for (int d4 = 0; d4 < 64; d4 += 4) {
            float4 a[8];
#pragma unroll
            for (int r = 0; r < 8; ++r)
                a[r] = *(const float4*)&sQ[(rowb + r) * Dc + d4];
            const int g0 = ((tx ^ ((d4 >> 2) & 15)) << 2);
#pragma unroll
            for (int t = 0; t < 4; ++t) {
                const ulonglong2 b0 = *(const ulonglong2*)&sK[(d4 + t) * KT + g0];
                const ulonglong2 b1 = *(const ulonglong2*)&sK[(d4 + t) * KT + 64 + g0];
#pragma unroll
                for (int r = 0; r < 8; ++r) {
                    u64 ad = dup2(f4c(a[r], t));
                    fma2(c2[r][0], ad, b0.x);
                    fma2(c2[r][1], ad, b0.y);
                    fma2(c2[r][2], ad, b1.x);
                    fma2(c2[r][3], ad, b1.y);
                }
            }
        }

        // ---- online softmax + dropout; exp gated, reductions use half-mask ----
        int anykept = 0;
#pragma unroll
        for (int r = 0; r < 8; ++r) {
            float s8[8];
            unpack2(c2[r][0], s8[0], s8[1]);
            unpack2(c2[r][1], s8[2], s8[3]);
            unpack2(c2[r][2], s8[4], s8[5]);
            unpack2(c2[r][3], s8[6], s8[7]);
            float tm8 = fmaxf(fmaxf(fmaxf(s8[0], s8[1]), fmaxf(s8[2], s8[3])),
                              fmaxf(fmaxf(s8[4], s8[5]), fmaxf(s8[6], s8[7])));
            float tm = tm8;
            // convergent execution: 16-lane max reduction (legal with hm too)
#pragma unroll
            for (int s = 1; s < 16; s <<= 1)
                tm = fmaxf(tm, __shfl_xor_sync(hm, tm, s));

            if (tm > m[r] - 28.f) {              // uniform within 16-lane half
                float mn = fmaxf(m[r], tm);
                float alpha = __expf(m[r] - mn);
                float rs = 0.f;
                if (tm8 > mn - 28.f) {           // this thread's chunk significant
#pragma unroll
                    for (int j = 0; j < 8; ++j) {
                        float e = __expf(s8[j] - mn);
                        s8[j] = e; rs += e;
                    }
                } else {
#pragma unroll
                    for (int j = 0; j < 8; ++j) s8[j] = 0.f;
                }
                // divergent region: MUST use the 16-lane member mask
#pragma unroll
                for (int s = 1; s < 16; s <<= 1)
                    rs += __shfl_xor_sync(hm, rs, s);
                l[r] = l[r] * alpha + rs;
                m[r] = mn;
                u64 a2 = dup2(alpha);
                o2[r][0] = mul2(o2[r][0], a2);
                o2[r][1] = mul2(o2[r][1], a2);

                // dropout: threefry only for survivors (~5 per full row)
                uint32_t gqr = (uint32_t)(q0 + rowb + r);
#pragma unroll
                for (int j = 0; j < 8; ++j) {
                    float p = s8[j];
                    float op = 0.f;
                    if (p > 1e-12f) {
                        uint32_t gkc = (uint32_t)(kt * KT +
                            ((j < 4) ? (tx * 4 + j) : (64 + tx * 4 + (j - 4))));
                        if (keep_mask(bh, gqr, gkc)) { op = p * 10.f; anykept = 1; }
                    }
                    s8[j] = op;
                }
            } else {
#pragma unroll
                for (int j = 0; j < 8; ++j) s8[j] = 0.f;
            }
            // always store P row (zeros if insignificant) — warp-private slab
            *(float4*)&sP[(rowb + r) * KT + (tx << 2)] =
                make_float4(s8[0], s8[1], s8[2], s8[3]);
            *(float4*)&sP[(rowb + r) * KT + 64 + (tx << 2)] =
                make_float4(s8[4], s8[5], s8[6], s8[7]);
        }
        __syncwarp();

        // ---- per-warp exact PV skip (convergent full-warp vote) ----
        if (__any_sync(0xffffffffu, anykept)) {
#pragma unroll 2
            for (int k4 = 0; k4 < KT; k4 += 4) {
                float4 pa[8];
#pragma unroll
                for (int r = 0; r < 8; ++r)
                    pa[r] = *(const float4*)&sP[(rowb + r) * KT + k4];
#pragma unroll
                for (int t = 0; t < 4; ++t) {
                    const ulonglong2 vb2 =
                        *(const ulonglong2*)&sV[(k4 + t) * Dc + (tx << 2)];
#pragma unroll
                    for (int r = 0; r < 8; ++r) {
                        u64 ad = dup2(f4c(pa[r], t));
                        fma2(o2[r][0], ad, vb2.x);
                        fma2(o2[r][1], ad, vb2.y);
                    }
                }
            }
        }
    }

    // ---- epilogue ----
    float* ob = gout + ((size_t)bh * Sc + q0) * Dc;
#pragma unroll
    for (int r = 0; r < 8; ++r) {
        float il = 1.0f / l[r];
        float x0, x1, x2, x3;
        unpack2(o2[r][0], x0, x1);
        unpack2(o2[r][1], x2, x3);
        *(float4*)&ob[(rowb + r) * Dc + (tx << 2)] =
            make_float4(x0 * il, x1 * il, x2 * il, x3 * il);
    }
}

extern "C" void kernel_launch(void* const* d_in, const int* in_sizes, int n_in,
                              void* d_out, int out_size)
{
    (void)in_sizes; (void)n_in; (void)out_size;
    const float* q = (const float*)d_in[0];
    const float* k = (const float*)d_in[1];
    const float* v = (const float*)d_in[2];
    float* o = (float*)d_out;

    size_t smem = SMEM_FLOATS * sizeof(float);   // 163840 B
    cudaFuncSetAttribute(attn_kernel,
                         cudaFuncAttributeMaxDynamicSharedMemorySize, (int)smem);
    dim3 grid(Sc / QT, Bc * Hc);
    attn_kernel<<<grid, NT, smem>>>(q, k, v, o);
}